// round 4
// baseline (speedup 1.0000x reference)
#include <cuda_runtime.h>
#include <cstdint>

// B=256, T=64 (K), S=16, U=4 -> P=256 pixels, O=1024 outputs/pixel.
//
// kernel 1: transpose+permute x (B,T,S,S) -> g_xTp[p][fragment-order], tf32-rounded.
//           Fragment order: [mtile=b>>4][kstep=t>>3][lane][reg] so the GEMM reads
//           each thread's {a0,a1,a2,a3} m16n8k8 fragment as ONE LDS.128.
// kernel 2: CTA = (n-tile, m-tile, pixel), 128x128x64 one-shot GEMM via
//           mma.sync.m16n8k8 tf32. W staged to smem in fragment order ({b0,b1}
//           as one LDS.64), tf32-rounded during staging (off the MMA chain).
//           One __syncthreads per CTA. Epilogue scatters into pixel-shuffle layout.

__device__ float g_xTp[256 * 256 * 64];  // [p][mtile 16][kstep 8][lane 32][reg 4]

__device__ __forceinline__ unsigned f2tf32(float f) {
    unsigned r; asm("cvt.rna.tf32.f32 %0, %1;" : "=r"(r) : "f"(f)); return r;
}
__device__ __forceinline__ uint32_t smem_u32(const void* p) {
    uint32_t a;
    asm("{ .reg .u64 t; cvta.to.shared.u64 t, %1; cvt.u32.u64 %0, t; }" : "=r"(a) : "l"(p));
    return a;
}
__device__ __forceinline__ void cp16(uint32_t sdst, const float* g) {
    asm volatile("cp.async.cg.shared.global [%0], [%1], 16;" :: "r"(sdst), "l"(g));
}

// Fragment-order offset for A element (row b in 0..255, k t in 0..63) within one pixel:
// mtile = b>>4, rr = b&15; kstep = t>>3, kc = t&7
// lane = (rr&7)*4 + (kc&3);  reg = ((kc>>2)<<1) | (rr>>3)
__device__ __forceinline__ int perm_off(int b, int t) {
    return ((b >> 4) << 10) + ((t >> 3) << 7) +
           (((b & 7) * 4 + (t & 3)) << 2) + (((t >> 2) & 1) << 1) + ((b >> 3) & 1);
}

// ---------------------------------------------------------------------------
// Transpose + permute: x[b*16384 + t*256 + p] -> g_xTp[p*16384 + perm_off(b,t)]
// ---------------------------------------------------------------------------
__global__ void transpose_kernel(const float* __restrict__ x) {
    __shared__ float tile[32][33];
    int p0 = blockIdx.x * 32, t0 = blockIdx.y * 32, b = blockIdx.z;
    int tx = threadIdx.x, ty = threadIdx.y;
    const float* src = x + (size_t)b * 16384 + (size_t)t0 * 256 + p0;
#pragma unroll
    for (int k = 0; k < 4; k++) {
        int t = ty + k * 8;
        tile[t][tx] = __uint_as_float(f2tf32(src[t * 256 + tx]));  // coalesced over p
    }
    __syncthreads();
#pragma unroll
    for (int k = 0; k < 4; k++) {
        int pl = ty + k * 8;                       // pixel within tile
        int p = p0 + pl;
        int t = t0 + tx;
        g_xTp[(size_t)p * 16384 + perm_off(b, t)] = tile[tx][pl];
    }
}

// ---------------------------------------------------------------------------
// GEMM: C[128(b) x 128(o)] = A[128x64] @ W[128x64]^T + bias, per pixel.
// 256 threads = 8 warps (2m x 4n), warp tile 64x32, m16n8k8 tf32.
// ---------------------------------------------------------------------------
#define AS_FLOATS 8192
#define WS_FLOATS 8192
#define SMEM_BYTES ((AS_FLOATS + WS_FLOATS + 128) * 4)

__global__ __launch_bounds__(256, 2) void gemm_kernel(const float* __restrict__ Wg_all,
                                                      const float* __restrict__ bias,
                                                      float* __restrict__ out) {
    extern __shared__ float smem[];
    float* As = smem;                       // [8 mtiles][8 ksteps][32 lanes][4]
    float* Ws = smem + AS_FLOATS;           // [16 ntiles][8 ksteps][32 lanes][2]
    float* bias_s = smem + AS_FLOATS + WS_FLOATS;  // [128]

    const int bn = blockIdx.x;   // 0..7
    const int bm = blockIdx.y;   // 0..1
    const int p  = blockIdx.z;
    const int tid = threadIdx.x;
    const int lane = tid & 31, warp = tid >> 5;
    const int wm = warp >> 2, wn = warp & 3;
    const int qr = lane >> 2, qc = lane & 3;

    // A: pre-permuted, contiguous 32KB block per (p, bm) -> straight cp.async copy
    const float* Ag = g_xTp + ((size_t)p << 14) + (bm << 13);
    uint32_t sA = smem_u32(As);
#pragma unroll
    for (int i = 0; i < 8; i++) {
        int idx = tid + i * 256;
        cp16(sA + idx * 16, Ag + idx * 4);
    }
    if (tid < 32) cp16(smem_u32(bias_s) + tid * 16, bias + (size_t)p * 1024 + bn * 128 + tid * 4);
    asm volatile("cp.async.commit_group;");

    // W: LDG.128 coalesced -> tf32 round -> STS scatter into fragment order
    const float* Wg = Wg_all + ((size_t)p << 16) + (size_t)(bn * 128) * 64;
#pragma unroll
    for (int i = 0; i < 8; i++) {
        int idx = tid + i * 256;          // 2048 float4s
        int r = idx >> 4;                 // 0..127 (o row)
        int c = (idx & 15) << 2;          // 0..60  (k)
        float4 v = *(const float4*)(Wg + r * 64 + c);
        int base = ((r >> 3) << 9) + ((c >> 3) << 6) + ((c >> 2) & 1) + ((r & 7) << 3);
        Ws[base + 0] = __uint_as_float(f2tf32(v.x));
        Ws[base + 2] = __uint_as_float(f2tf32(v.y));
        Ws[base + 4] = __uint_as_float(f2tf32(v.z));
        Ws[base + 6] = __uint_as_float(f2tf32(v.w));
    }
    asm volatile("cp.async.wait_group 0;");
    __syncthreads();

    float acc[4][4][4];
#pragma unroll
    for (int mi = 0; mi < 4; mi++)
#pragma unroll
        for (int ni = 0; ni < 4; ni++)
#pragma unroll
            for (int q = 0; q < 4; q++) acc[mi][ni][q] = 0.f;

    const float* Abase = As + lane * 4;                    // + mtile*1024 + ks*128
    const float* Bbase = Ws + (wn << 11) + lane * 2;       // + ni*512 + ks*64

#pragma unroll
    for (int ks = 0; ks < 8; ks++) {
        uint4 a[4];
        float2 b[4];
#pragma unroll
        for (int mi = 0; mi < 4; mi++)
            a[mi] = *(const uint4*)(Abase + ((wm * 4 + mi) << 10) + (ks << 7));
#pragma unroll
        for (int ni = 0; ni < 4; ni++)
            b[ni] = *(const float2*)(Bbase + (ni << 9) + (ks << 6));
#pragma unroll
        for (int mi = 0; mi < 4; mi++)
#pragma unroll
            for (int ni = 0; ni < 4; ni++) {
                asm("mma.sync.aligned.m16n8k8.row.col.f32.tf32.tf32.f32 "
                    "{%0,%1,%2,%3}, {%4,%5,%6,%7}, {%8,%9}, {%0,%1,%2,%3};"
                    : "+f"(acc[mi][ni][0]), "+f"(acc[mi][ni][1]),
                      "+f"(acc[mi][ni][2]), "+f"(acc[mi][ni][3])
                    : "r"(a[mi].x), "r"(a[mi].y), "r"(a[mi].z), "r"(a[mi].w),
                      "r"(__float_as_uint(b[ni].x)), "r"(__float_as_uint(b[ni].y)));
            }
    }

    // Epilogue: o = bn*128 + o_loc; o viewed as (t, ui, uj); out is (256,64,64,64)
    const int i4 = (p >> 4) << 2, j4 = (p & 15) << 2;
#pragma unroll
    for (int ni = 0; ni < 4; ni++) {
        int o_loc = wn * 32 + ni * 8 + 2 * qc;
        int o = bn * 128 + o_loc;
        int t  = o >> 4;
        int ui = (o >> 2) & 3;
        int uj = o & 3;
        int coloff = t * 4096 + (i4 + ui) * 64 + j4 + uj;
        float b0 = bias_s[o_loc];
        float b1 = bias_s[o_loc + 1];
#pragma unroll
        for (int mi = 0; mi < 4; mi++) {
            int row = bm * 128 + wm * 64 + mi * 16 + qr;
            *(float2*)(out + (size_t)row * 262144 + coloff) =
                make_float2(acc[mi][ni][0] + b0, acc[mi][ni][1] + b1);
            *(float2*)(out + (size_t)(row + 8) * 262144 + coloff) =
                make_float2(acc[mi][ni][2] + b0, acc[mi][ni][3] + b1);
        }
    }
}

extern "C" void kernel_launch(void* const* d_in, const int* in_sizes, int n_in,
                              void* d_out, int out_size) {
    const float* x = (const float*)d_in[0];   // (256, 64, 16, 16)
    const float* W = (const float*)d_in[1];   // (256, 1024, 64)
    const float* b = (const float*)d_in[2];   // (256, 1024)
    float* out = (float*)d_out;               // (256, 64, 64, 64)
    (void)in_sizes; (void)n_in; (void)out_size;

    cudaFuncSetAttribute(gemm_kernel, cudaFuncAttributeMaxDynamicSharedMemorySize, SMEM_BYTES);

    transpose_kernel<<<dim3(8, 2, 256), dim3(32, 8)>>>(x);
    gemm_kernel<<<dim3(8, 2, 256), 256, SMEM_BYTES>>>(W, b, out);
}

// round 5
// speedup vs baseline: 1.0273x; 1.0273x over previous
#include <cuda_runtime.h>
#include <cstdint>

// B=256, T=64 (K), S=16, U=4 -> P=256 pixels, O=1024 outputs/pixel.
//
// kernel 1: transpose+permute x (B,T,S,S) -> g_xTp[p][fragment-order], tf32-rounded.
// kernel 2: CTA = (n-tile 16, m-tile 2, pixel 256), 128x64x64 GEMM via
//           mma.sync.m16n8k8 tf32, warp tile 32x32, 8 warps, 3 CTAs/SM for
//           latency hiding. Epilogue scatters into pixel-shuffle layout.

__device__ float g_xTp[256 * 256 * 64];  // [p][mtile 16][kstep 8][lane 32][reg 4]

__device__ __forceinline__ unsigned f2tf32(float f) {
    unsigned r; asm("cvt.rna.tf32.f32 %0, %1;" : "=r"(r) : "f"(f)); return r;
}
__device__ __forceinline__ uint32_t smem_u32(const void* p) {
    uint32_t a;
    asm("{ .reg .u64 t; cvta.to.shared.u64 t, %1; cvt.u32.u64 %0, t; }" : "=r"(a) : "l"(p));
    return a;
}
__device__ __forceinline__ void cp16(uint32_t sdst, const float* g) {
    asm volatile("cp.async.cg.shared.global [%0], [%1], 16;" :: "r"(sdst), "l"(g));
}

// Fragment-order offset for A element (row b in 0..255, k t in 0..63) within one pixel.
__device__ __forceinline__ int perm_off(int b, int t) {
    return ((b >> 4) << 10) + ((t >> 3) << 7) +
           (((b & 7) * 4 + (t & 3)) << 2) + (((t >> 2) & 1) << 1) + ((b >> 3) & 1);
}

// ---------------------------------------------------------------------------
// Transpose + permute: x[b*16384 + t*256 + p] -> g_xTp[p*16384 + perm_off(b,t)]
// ---------------------------------------------------------------------------
__global__ void transpose_kernel(const float* __restrict__ x) {
    __shared__ float tile[32][33];
    int p0 = blockIdx.x * 32, t0 = blockIdx.y * 32, b = blockIdx.z;
    int tx = threadIdx.x, ty = threadIdx.y;
    const float* src = x + (size_t)b * 16384 + (size_t)t0 * 256 + p0;
#pragma unroll
    for (int k = 0; k < 4; k++) {
        int t = ty + k * 8;
        tile[t][tx] = __uint_as_float(f2tf32(src[t * 256 + tx]));  // coalesced over p
    }
    __syncthreads();
#pragma unroll
    for (int k = 0; k < 4; k++) {
        int pl = ty + k * 8;
        int p = p0 + pl;
        int t = t0 + tx;
        g_xTp[(size_t)p * 16384 + perm_off(b, t)] = tile[tx][pl];
    }
}

// ---------------------------------------------------------------------------
// GEMM: C[128(b) x 64(o)] = A[128x64] @ W[64x64]^T + bias, per pixel.
// 256 threads = 8 warps (4m x 2n), warp tile 32x32, m16n8k8 tf32.
// ---------------------------------------------------------------------------
#define AS_FLOATS 8192   // 8 mtiles x 8 ksteps x 32 lanes x 4
#define WS_FLOATS 4096   // 8 ntiles x 8 ksteps x 32 lanes x 2
#define SMEM_BYTES ((AS_FLOATS + WS_FLOATS + 64) * 4)

__global__ __launch_bounds__(256, 3) void gemm_kernel(const float* __restrict__ Wg_all,
                                                      const float* __restrict__ bias,
                                                      float* __restrict__ out) {
    extern __shared__ float smem[];
    float* As = smem;                        // [8][8][32][4]
    float* Ws = smem + AS_FLOATS;            // [8][8][32][2]
    float* bias_s = smem + AS_FLOATS + WS_FLOATS;  // [64]

    const int bn = blockIdx.x;   // 0..15
    const int bm = blockIdx.y;   // 0..1
    const int p  = blockIdx.z;
    const int tid = threadIdx.x;
    const int lane = tid & 31, warp = tid >> 5;
    const int wm = warp >> 1, wn = warp & 1;   // 4m x 2n
    const int qr = lane >> 2, qc = lane & 3;

    // A: pre-permuted; contiguous 32KB block per (p, bm)
    const float* Ag = g_xTp + ((size_t)p << 14) + (bm << 13);
    uint32_t sA = smem_u32(As);
#pragma unroll
    for (int i = 0; i < 8; i++) {
        int idx = tid + i * 256;
        cp16(sA + idx * 16, Ag + idx * 4);
    }
    if (tid < 16) cp16(smem_u32(bias_s) + tid * 16, bias + (size_t)p * 1024 + bn * 64 + tid * 4);
    asm volatile("cp.async.commit_group;");

    // W: LDG.128 coalesced -> tf32 round -> STS scatter into fragment order
    const float* Wg = Wg_all + ((size_t)p << 16) + (size_t)(bn * 64) * 64;
#pragma unroll
    for (int i = 0; i < 4; i++) {
        int idx = tid + i * 256;          // 1024 float4s (64 rows x 64 k)
        int r = idx >> 4;                 // 0..63  (o row)
        int c = (idx & 15) << 2;          // 0..60  (k)
        float4 v = *(const float4*)(Wg + r * 64 + c);
        int base = ((r >> 3) << 9) + ((c >> 3) << 6) + ((c >> 2) & 1) + ((r & 7) << 3);
        Ws[base + 0] = __uint_as_float(f2tf32(v.x));
        Ws[base + 2] = __uint_as_float(f2tf32(v.y));
        Ws[base + 4] = __uint_as_float(f2tf32(v.z));
        Ws[base + 6] = __uint_as_float(f2tf32(v.w));
    }
    asm volatile("cp.async.wait_group 0;");
    __syncthreads();

    float acc[2][4][4];
#pragma unroll
    for (int mi = 0; mi < 2; mi++)
#pragma unroll
        for (int ni = 0; ni < 4; ni++)
#pragma unroll
            for (int q = 0; q < 4; q++) acc[mi][ni][q] = 0.f;

    const float* Abase = As + ((wm * 2) << 10) + lane * 4;   // + mi*1024 + ks*128
    const float* Bbase = Ws + ((wn * 4) << 9) + lane * 2;    // + ni*512 + ks*64

#pragma unroll
    for (int ks = 0; ks < 8; ks++) {
        uint4 a[2];
        float2 b[4];
#pragma unroll
        for (int mi = 0; mi < 2; mi++)
            a[mi] = *(const uint4*)(Abase + (mi << 10) + (ks << 7));
#pragma unroll
        for (int ni = 0; ni < 4; ni++)
            b[ni] = *(const float2*)(Bbase + (ni << 9) + (ks << 6));
#pragma unroll
        for (int mi = 0; mi < 2; mi++)
#pragma unroll
            for (int ni = 0; ni < 4; ni++) {
                asm("mma.sync.aligned.m16n8k8.row.col.f32.tf32.tf32.f32 "
                    "{%0,%1,%2,%3}, {%4,%5,%6,%7}, {%8,%9}, {%0,%1,%2,%3};"
                    : "+f"(acc[mi][ni][0]), "+f"(acc[mi][ni][1]),
                      "+f"(acc[mi][ni][2]), "+f"(acc[mi][ni][3])
                    : "r"(a[mi].x), "r"(a[mi].y), "r"(a[mi].z), "r"(a[mi].w),
                      "r"(__float_as_uint(b[ni].x)), "r"(__float_as_uint(b[ni].y)));
            }
    }

    // Epilogue: o = bn*64 + o_loc; o viewed as (t, ui, uj); out is (256,64,64,64)
    const int i4 = (p >> 4) << 2, j4 = (p & 15) << 2;
#pragma unroll
    for (int ni = 0; ni < 4; ni++) {
        int o_loc = wn * 32 + ni * 8 + 2 * qc;
        int o = bn * 64 + o_loc;
        int t  = o >> 4;
        int ui = (o >> 2) & 3;
        int uj = o & 3;
        int coloff = t * 4096 + (i4 + ui) * 64 + j4 + uj;
        float b0 = bias_s[o_loc];
        float b1 = bias_s[o_loc + 1];
#pragma unroll
        for (int mi = 0; mi < 2; mi++) {
            int row = bm * 128 + wm * 32 + mi * 16 + qr;
            *(float2*)(out + (size_t)row * 262144 + coloff) =
                make_float2(acc[mi][ni][0] + b0, acc[mi][ni][1] + b1);
            *(float2*)(out + (size_t)(row + 8) * 262144 + coloff) =
                make_float2(acc[mi][ni][2] + b0, acc[mi][ni][3] + b1);
        }
    }
}

extern "C" void kernel_launch(void* const* d_in, const int* in_sizes, int n_in,
                              void* d_out, int out_size) {
    const float* x = (const float*)d_in[0];   // (256, 64, 16, 16)
    const float* W = (const float*)d_in[1];   // (256, 1024, 64)
    const float* b = (const float*)d_in[2];   // (256, 1024)
    float* out = (float*)d_out;               // (256, 64, 64, 64)
    (void)in_sizes; (void)n_in; (void)out_size;

    cudaFuncSetAttribute(gemm_kernel, cudaFuncAttributeMaxDynamicSharedMemorySize, SMEM_BYTES);

    transpose_kernel<<<dim3(8, 2, 256), dim3(32, 8)>>>(x);
    gemm_kernel<<<dim3(16, 2, 256), 256, SMEM_BYTES>>>(W, b, out);
}